// round 2
// baseline (speedup 1.0000x reference)
#include <cuda_runtime.h>

#define Bsz 2048
#define Tsz 512
#define Asz 32
#define Hsz 16

typedef unsigned long long u64;

__device__ __forceinline__ u64 pack2(float lo, float hi) {
    u64 r; asm("mov.b64 %0, {%1, %2};" : "=l"(r) : "f"(lo), "f"(hi)); return r;
}
__device__ __forceinline__ void unpack2(u64 v, float& lo, float& hi) {
    asm("mov.b64 {%0, %1}, %2;" : "=f"(lo), "=f"(hi) : "l"(v));
}
__device__ __forceinline__ u64 fma2(u64 a, u64 b, u64 c) {
    u64 d; asm("fma.rn.f32x2 %0, %1, %2, %3;" : "=l"(d) : "l"(a), "l"(b), "l"(c)); return d;
}
__device__ __forceinline__ u64 add2(u64 a, u64 b) {
    u64 d; asm("add.rn.f32x2 %0, %1, %2;" : "=l"(d) : "l"(a), "l"(b)); return d;
}
__device__ __forceinline__ float sigmoidf_(float x) {
    return __fdividef(1.0f, 1.0f + __expf(-x));
}

// smem layouts (per CTA of 4 warps)
//  hring[w][8][16] : h history ring (64B rows, broadcast reads)
//  xring[w][2][32] : x staging double buffer (128B rows)
//  wact  [32][20]  : actor weights, 20-float padded rows (80B, 16B aligned)

__global__ void __launch_bounds__(128, 4) lstm_fused_kernel(
    const float* __restrict__ xin, const float* __restrict__ masks,
    const float* __restrict__ h0, const float* __restrict__ c0,
    const float* __restrict__ w_ih, const float* __restrict__ w_hh,
    const float* __restrict__ b_ih, const float* __restrict__ b_hh,
    const float* __restrict__ w_actor, const float* __restrict__ b_actor,
    const float* __restrict__ w_critic, const float* __restrict__ b_critic,
    float* __restrict__ actor, float* __restrict__ critic,
    float* __restrict__ hT, float* __restrict__ cT)
{
    __shared__ __align__(16) float hring[4][8][16];
    __shared__ __align__(16) float xring[4][2][32];
    __shared__ __align__(16) float wact_s[32][20];

    const int tid  = threadIdx.x;
    const int w    = tid >> 5;
    const int lane = tid & 31;
    const int j    = lane & 15;
    const bool hi  = lane >= 16;
    const int b    = blockIdx.x * 4 + w;

    for (int i = tid; i < Asz * Hsz; i += 128)
        wact_s[i >> 4][i & 15] = w_actor[i];

    // gate rows (torch order i,f,g,o): lo lane j -> (i_j, g_j); hi lane 16+j -> (f_j, o_j)
    const int rowA = hi ? (16 + j) : j;
    const int rowB = hi ? (48 + j) : (32 + j);

    u64 wA2[16], wB2[16], wAh2[8], wBh2[8];
#pragma unroll
    for (int k = 0; k < 16; k++) {
        wA2[k] = pack2(w_ih[rowA * 32 + 2 * k], w_ih[rowA * 32 + 2 * k + 1]);
        wB2[k] = pack2(w_ih[rowB * 32 + 2 * k], w_ih[rowB * 32 + 2 * k + 1]);
    }
#pragma unroll
    for (int k = 0; k < 8; k++) {
        wAh2[k] = pack2(w_hh[rowA * 16 + 2 * k], w_hh[rowA * 16 + 2 * k + 1]);
        wBh2[k] = pack2(w_hh[rowB * 16 + 2 * k], w_hh[rowB * 16 + 2 * k + 1]);
    }
    const float biasA = b_ih[rowA] + b_hh[rowA];
    const float biasB = b_ih[rowB] + b_hh[rowB];
    const float bact  = b_actor[lane];
    const float wc    = hi ? w_critic[j] : 0.0f;
    const float bcr   = b_critic[0];

    const float* xb = xin + (size_t)b * Tsz * Asz;
    const float* mb = masks + (size_t)b * Tsz;
    float* actb     = actor + (size_t)b * Tsz * Asz;
    float* crb      = critic + (size_t)b * Tsz;

    float c = hi ? c0[b * Hsz + j] : 0.0f;
    if (hi) hring[w][7][j] = h0[b * Hsz + j];
    xring[w][0][lane] = xb[lane];          // x_0
    float xcar = xb[Asz + lane];           // x_1 carried in reg
    float m_cur = mb[0];
    __syncthreads();

    float h2 = 0.0f;

    for (int t = 0; t < Tsz; t++) {
        // prefetch (2 steps ahead for x via carry reg; 1 step for mask)
        const int tn = (t + 1 < Tsz) ? t + 1 : Tsz - 1;
        const int t2 = (t + 2 < Tsz) ? t + 2 : Tsz - 1;
        const float m_nxt = mb[tn];
        const float xnew  = xb[t2 * Asz + lane];

        // ---- x-part (independent of h): 32 packed FMAs
        const ulonglong2* xr = reinterpret_cast<const ulonglong2*>(&xring[w][t & 1][0]);
        u64 xA0 = pack2(biasA, 0.0f), xA1 = pack2(0.0f, 0.0f);
        u64 xB0 = pack2(biasB, 0.0f), xB1 = pack2(0.0f, 0.0f);
#pragma unroll
        for (int q = 0; q < 8; q++) {
            const ulonglong2 v = xr[q];
            xA0 = fma2(wA2[2 * q],     v.x, xA0);
            xA1 = fma2(wA2[2 * q + 1], v.y, xA1);
            xB0 = fma2(wB2[2 * q],     v.x, xB0);
            xB1 = fma2(wB2[2 * q + 1], v.y, xB1);
        }

        // ---- h-part: 16 packed FMAs (reads h_{t-1} ring slot)
        const ulonglong2* hr = reinterpret_cast<const ulonglong2*>(&hring[w][(t + 7) & 7][0]);
        u64 hA0 = pack2(0.0f, 0.0f), hA1 = pack2(0.0f, 0.0f);
        u64 hB0 = pack2(0.0f, 0.0f), hB1 = pack2(0.0f, 0.0f);
#pragma unroll
        for (int q = 0; q < 4; q++) {
            const ulonglong2 v = hr[q];
            hA0 = fma2(wAh2[2 * q],     v.x, hA0);
            hA1 = fma2(wAh2[2 * q + 1], v.y, hA1);
            hB0 = fma2(wBh2[2 * q],     v.x, hB0);
            hB1 = fma2(wBh2[2 * q + 1], v.y, hB1);
        }

        // gate = x_part + m * h_part   (mask folded algebraically)
        const u64 m2 = pack2(m_cur, m_cur);
        const u64 tA = fma2(m2, add2(hA0, hA1), add2(xA0, xA1));
        const u64 tB = fma2(m2, add2(hB0, hB1), add2(xB0, xB1));
        float aLo, aHi, bLo, bHi;
        unpack2(tA, aLo, aHi);
        unpack2(tB, bLo, bHi);
        const float gA = aLo + aHi;          // lo: i-gate, hi: f-gate
        const float gB = bLo + bHi;          // lo: g-gate, hi: o-gate

        const float vA = sigmoidf_(gA);
        // vB: hi -> sigmoid(gB) [o]; lo -> tanh(gB) = 2*sigmoid(2 gB) - 1 [g]
        const float sB = sigmoidf_(hi ? gB : 2.0f * gB);
        const float vB = hi ? sB : fmaf(2.0f, sB, -1.0f);

        const float p  = vA * vB;                         // lo lanes: i*g
        const float ig = __shfl_sync(0xffffffffu, p, j);  // hi lanes fetch i*g

        c = fmaf(vA, c * m_cur, ig);                      // c2 = f*(c*m) + i*g (hi lanes valid)
        const float tc = fmaf(2.0f, sigmoidf_(2.0f * c), -1.0f);  // tanh(c2)
        h2 = vB * tc;                                     // h2 = o*tanh(c2) (hi lanes valid)

        if (hi) hring[w][t & 7][j] = h2;
        xring[w][(t + 1) & 1][lane] = xcar;               // stage x_{t+1}
        __syncwarp();
        xcar  = xnew;
        m_cur = m_nxt;

        // ---- critic: reduce over hi half (4 butterflies), lane 16 stores
        float cp = hi ? h2 * wc : 0.0f;
        cp += __shfl_xor_sync(0xffffffffu, cp, 8);
        cp += __shfl_xor_sync(0xffffffffu, cp, 4);
        cp += __shfl_xor_sync(0xffffffffu, cp, 2);
        cp += __shfl_xor_sync(0xffffffffu, cp, 1);
        if (lane == 16) crb[t] = cp + bcr;

        // ---- actor head, batched over 8 steps (weight row loaded once per pass)
        if ((t & 7) == 7) {
            const ulonglong2* wrow = reinterpret_cast<const ulonglong2*>(&wact_s[lane][0]);
            const ulonglong2 w0 = wrow[0], w1 = wrow[1], w2 = wrow[2], w3 = wrow[3];
            const int t0 = t - 7;
#pragma unroll
            for (int k = 0; k < 8; k++) {
                const ulonglong2* hp = reinterpret_cast<const ulonglong2*>(&hring[w][k][0]);
                u64 a0 = pack2(bact, 0.0f);
                u64 a1 = pack2(0.0f, 0.0f);
                a0 = fma2(w0.x, hp[0].x, a0); a1 = fma2(w0.y, hp[0].y, a1);
                a0 = fma2(w1.x, hp[1].x, a0); a1 = fma2(w1.y, hp[1].y, a1);
                a0 = fma2(w2.x, hp[2].x, a0); a1 = fma2(w2.y, hp[2].y, a1);
                a0 = fma2(w3.x, hp[3].x, a0); a1 = fma2(w3.y, hp[3].y, a1);
                float s0, s1, s2, s3;
                unpack2(add2(a0, a1), s0, s1);
                actb[(t0 + k) * Asz + lane] = s0 + s1;
                (void)s2; (void)s3;
            }
        }
    }

    if (hi) {
        hT[b * Hsz + j] = h2;
        cT[b * Hsz + j] = c;
    }
}

extern "C" void kernel_launch(void* const* d_in, const int* in_sizes, int n_in,
                              void* d_out, int out_size) {
    const float* xin      = (const float*)d_in[0];
    const float* masks    = (const float*)d_in[1];
    const float* h0       = (const float*)d_in[2];
    const float* c0       = (const float*)d_in[3];
    const float* w_ih     = (const float*)d_in[4];
    const float* w_hh     = (const float*)d_in[5];
    const float* b_ih     = (const float*)d_in[6];
    const float* b_hh     = (const float*)d_in[7];
    const float* w_actor  = (const float*)d_in[8];
    const float* b_actor  = (const float*)d_in[9];
    const float* w_critic = (const float*)d_in[10];
    const float* b_critic = (const float*)d_in[11];

    float* out    = (float*)d_out;
    float* actor  = out;
    float* critic = actor + (size_t)Bsz * Tsz * Asz;
    float* hT     = critic + (size_t)Bsz * Tsz;
    float* cT     = hT + (size_t)Bsz * Hsz;

    lstm_fused_kernel<<<Bsz / 4, 128>>>(
        xin, masks, h0, c0, w_ih, w_hh, b_ih, b_hh,
        w_actor, b_actor, w_critic, b_critic,
        actor, critic, hT, cT);
}